// round 17
// baseline (speedup 1.0000x reference)
#include <cuda_runtime.h>
#include <cuda_fp16.h>
#include <cstdint>

#define Bv 128
#define Tv 4096
#define DIN 64
#define Hv 512
#define DOUT 64
#define NCTA 128
#define NTHR 320            // 8 compute warps (4/stream) + 2 producer warps
#define K1 576
#define K2 1024
#define K1PH 584            // weight row stride (halfs) -> conflict-free B-frag LDS
#define K2PH 1032
#define NRING 4             // per-stream ring of big buffers
#define H1D 8               // h1 ring depth (power of 2)
#define GW 72               // row stride (halfs) -> conflict-free A-frag LDS
#define HC_W (64 * GW)      // half-chunk (64 rows) in halfs
#define HC_BYTES (HC_W * 2)         // 9216
#define BIGH_W (2 * HC_W)           // big chunk (128 k-cols, one stream)
#define BIGH_BYTES (2 * HC_BYTES)   // 18432
#define OW 68               // out_gemm smem stride (floats)
#define FLG 64              // flag spacing (words) = 256B
#define SMEM_BYTES (2*NRING*BIGH_BYTES + 16*K1PH*2 + 16*K2PH*2 + 1024*4 + 32*4 + 256)

// Persistent scratch (static __device__: the sanctioned allocation path)
__device__ __half g_xT[(size_t)Tv * 2 * HC_W];                   // x: [t][s][64][GW]
__device__ __half g_h1[H1D][2][8][64][GW];                       // h1 ring, stream-major
__device__ __half g_h2all[(size_t)(Tv + 1) * 2 * 8 * HC_W];      // h2: slot p = h2(p-1)
__device__ unsigned g_flag[NCTA * 2 * FLG];                      // per-CTA-per-stream flags

__device__ __forceinline__ float sigm(float x) { return 1.0f / (1.0f + __expf(-x)); }
__device__ __forceinline__ float tanh_(float x) { return 1.0f - 2.0f / (__expf(2.0f * x) + 1.0f); }

__device__ __forceinline__ unsigned ld_acq(const unsigned* p) {
    unsigned v;
    asm volatile("ld.acquire.gpu.global.b32 %0, [%1];" : "=r"(v) : "l"(p));
    return v;
}
__device__ __forceinline__ void st_rel(unsigned* p, unsigned v) {
    asm volatile("st.release.gpu.global.b32 [%0], %1;" :: "l"(p), "r"(v) : "memory");
}
__device__ __forceinline__ void issue_big(unsigned sdst, const void* gsrc, unsigned mbar,
                                          unsigned bytes) {
    asm volatile("mbarrier.arrive.expect_tx.shared.b64 _, [%0], %1;"
                 :: "r"(mbar), "r"(bytes) : "memory");
    asm volatile("cp.async.bulk.shared::cta.global.mbarrier::complete_tx::bytes [%0], [%1], %2, [%3];"
                 :: "r"(sdst), "l"(gsrc), "r"(bytes), "r"(mbar) : "memory");
}
__device__ __forceinline__ void mbar_wait(unsigned mbar, unsigned parity) {
    asm volatile(
        "{\n\t.reg .pred P;\n"
        "W%=:\n\t"
        "mbarrier.try_wait.parity.acquire.cta.shared::cta.b64 P, [%0], %1, 0x989680;\n\t"
        "@!P bra W%=;\n\t}"
        :: "r"(mbar), "r"(parity) : "memory");
}
__device__ __forceinline__ void mbar_arrive(unsigned mbar) {
    asm volatile("mbarrier.arrive.shared.b64 _, [%0];" :: "r"(mbar) : "memory");
}

// One-time x transpose + fp16 round: x[b][t][64] -> xT[t][stream][64][GW]
__global__ void __launch_bounds__(256)
xpose(const float* __restrict__ x) {
    const int t = blockIdx.x;
    for (int i = threadIdx.x; i < 128 * 16; i += 256) {
        int b = i >> 4, j = i & 15;
        int s = b >> 6, lr = b & 63;
        float4 v = *(const float4*)(x + ((size_t)b * Tv + t) * 64 + j * 4);
        __half2* dst = (__half2*)(g_xT + ((size_t)t * 2 + s) * HC_W + lr * GW + j * 4);
        dst[0] = __floats2half2_rn(v.x, v.y);
        dst[1] = __floats2half2_rn(v.z, v.w);
    }
}

__global__ void __launch_bounds__(NTHR, 1)
lstm_kernel(const float* __restrict__ w_ih1, const float* __restrict__ w_hh1,
            const float* __restrict__ b_ih1, const float* __restrict__ b_hh1,
            const float* __restrict__ w_ih2, const float* __restrict__ w_hh2,
            const float* __restrict__ b_ih2, const float* __restrict__ b_hh2) {
    extern __shared__ __half smh[];
    __half* swl1 = smh + 2 * NRING * BIGH_W;         // L1 weights [16][K1PH]
    __half* swl2 = swl1 + 16 * K1PH;                 // L2 weights [16][K2PH]
    float* sc = (float*)(swl2 + 16 * K2PH);          // c-state [2][128][4]
    float* sb = sc + 1024;                           // fused biases [2][16]
    float* mbf = sb + 32;                            // full[8]@+0, consumed[8]@+64
    __shared__ unsigned s_e0[2];

    const int tid = threadIdx.x;
    const int cl = blockIdx.x;
    const int u0 = cl * 4;                           // 4 units per layer per CTA
    const int lane = tid & 31, warp = tid >> 5;
    const int c4 = lane & 3, q = lane >> 2;
    const unsigned smem_base = (unsigned)__cvta_generic_to_shared(smh);
    const unsigned mb = (unsigned)__cvta_generic_to_shared(mbf);
    const int ch = u0 >> 6, colbase = u0 & 63;

    if (tid == 0) {
        s_e0[0] = ld_acq(&g_flag[(cl * 2 + 0) * FLG]);
        s_e0[1] = ld_acq(&g_flag[(cl * 2 + 1) * FLG]);
#pragma unroll
        for (int b = 0; b < 8; b++) {
            asm volatile("mbarrier.init.shared.b64 [%0], 1;" :: "r"(mb + b * 8) : "memory");
            asm volatile("mbarrier.init.shared.b64 [%0], 4;" :: "r"(mb + 64 + b * 8) : "memory");
        }
        asm volatile("fence.proxy.async.shared::cta;" ::: "memory");
    }

    // ---- stage weight slices (fp16) + fused biases ----
    // row r = pair*8 + sub*4 + gate ; unit = pair*2 + sub ; jg = gate*Hv + u0 + unit
    for (int idx = tid; idx < 16 * K1; idx += NTHR) {
        int r = idx / K1, k = idx - r * K1;
        int gate = r & 3, sub = (r >> 2) & 1, pair = r >> 3;
        int jg = gate * Hv + u0 + pair * 2 + sub;
        float wv = (k < DIN) ? w_ih1[jg * DIN + k] : w_hh1[(size_t)jg * Hv + (k - DIN)];
        swl1[r * K1PH + k] = __float2half_rn(wv);
    }
    for (int idx = tid; idx < 16 * K2; idx += NTHR) {
        int r = idx >> 10, k = idx & 1023;
        int gate = r & 3, sub = (r >> 2) & 1, pair = r >> 3;
        int jg = gate * Hv + u0 + pair * 2 + sub;
        float wv = (k < Hv) ? w_ih2[(size_t)jg * Hv + k] : w_hh2[(size_t)jg * Hv + (k - Hv)];
        swl2[r * K2PH + k] = __float2half_rn(wv);
    }
    if (tid < 32) {
        int layer = tid >> 4, r = tid & 15;
        int gate = r & 3, sub = (r >> 2) & 1, pair = r >> 3;
        int jg = gate * Hv + u0 + pair * 2 + sub;
        sb[tid] = layer ? (b_ih2[jg] + b_hh2[jg]) : (b_ih1[jg] + b_hh1[jg]);
    }
    for (int i = tid; i < 1024; i += NTHR) sc[i] = 0.0f;

    // ---- zero OWN slices: h1 ring slot H1D-1, h2 slot 0 (4 cols each) ----
    if (tid < 128) {
        int s = tid >> 6, lr = tid & 63;
        *(uint64_t*)&g_h1[H1D - 1][s][ch][lr][colbase] = 0ull;
        *(uint64_t*)(g_h2all + ((size_t)0 * 2 + s) * 8 * HC_W + ch * HC_W
                     + (size_t)lr * GW + colbase) = 0ull;
    }
    __syncthreads();
    if (tid == 0) {
        __threadfence();
        st_rel(&g_flag[(cl * 2 + 0) * FLG], s_e0[0] + 1);
        st_rel(&g_flag[(cl * 2 + 1) * FLG], s_e0[1] + 1);
    }
    __syncthreads();

    if (warp >= 8) {
        // ================= PRODUCER WARPS (8: stream 0, 9: stream 1) =================
        const int s = warp - 8;
        const unsigned E0 = s_e0[s];
        const unsigned fullb0 = mb + s * NRING * 8;
        const unsigned consb0 = mb + 64 + s * NRING * 8;
        const unsigned cbase = smem_base + s * NRING * BIGH_BYTES;
        const unsigned* f0 = &g_flag[((lane) * 2 + s) * FLG];
        const unsigned* f1 = &g_flag[((lane + 32) * 2 + s) * FLG];
        const unsigned* f2 = &g_flag[((lane + 64) * 2 + s) * FLG];
        const unsigned* f3 = &g_flag[((lane + 96) * 2 + s) * FLG];
        unsigned gidx = 0;
        for (int p = 0; p <= Tv; p++) {
            const bool doL1 = p < Tv, doL2 = p >= 1;
            const unsigned T = E0 + (unsigned)p + 1u;
            if (doL1) {   // x chunk: no data deps, issue pre-poll
                const __half* srcX = g_xT + ((size_t)p * 2 + s) * HC_W;
                const unsigned sl = gidx & 3, m = gidx >> 2;
                if (lane == 0) {
                    if (m >= 1) mbar_wait(consb0 + sl * 8, (m - 1) & 1u);
                    issue_big(cbase + sl * BIGH_BYTES, srcX, fullb0 + sl * 8, HC_BYTES);
                }
                __syncwarp();
                gidx++;
            }
            // one wide poll: all 128 CTA flags (4 per lane, concurrent)
            while (true) {
                unsigned v0 = ld_acq(f0), v1 = ld_acq(f1);
                unsigned v2 = ld_acq(f2), v3 = ld_acq(f3);
                if ((int)(v0 - T) >= 0 && (int)(v1 - T) >= 0 &&
                    (int)(v2 - T) >= 0 && (int)(v3 - T) >= 0) break;
            }
            __syncwarp();
            const __half* srcH1 = &g_h1[(p - 1) & (H1D - 1)][s][0][0][0];
            const __half* srcH2 = g_h2all + ((size_t)(p - 1) * 2 + s) * 8 * HC_W;
            const int cend = doL2 ? 9 : 5;
            for (int c = 1; c < cend; c++) {
                const __half* src = (c <= 4) ? srcH1 + (size_t)(c - 1) * BIGH_W
                                             : srcH2 + (size_t)(c - 5) * BIGH_W;
                const unsigned sl = gidx & 3, m = gidx >> 2;
                if (lane == 0) {
                    if (m >= 1) mbar_wait(consb0 + sl * 8, (m - 1) & 1u);
                    issue_big(cbase + sl * BIGH_BYTES, src, fullb0 + sl * 8, BIGH_BYTES);
                }
                __syncwarp();
                gidx++;
            }
        }
    } else {
        // ================= COMPUTE WARPS: 0-3 stream 0, 4-7 stream 1 =================
        const int s = warp >> 2;
        const unsigned E0 = s_e0[s];
        const int wl = warp & 3;
        const int r0 = wl * 16 + q, r1 = r0 + 8;
        const unsigned fullb0 = mb + s * NRING * 8;
        const unsigned consb0 = mb + 64 + s * NRING * 8;
        __half* chunks = smh + s * NRING * BIGH_W;
        unsigned* myflag = &g_flag[(cl * 2 + s) * FLG];
        unsigned phbits = 0, gidx = 0;
        for (int p = 0; p <= Tv; p++) {
            const bool doL1 = p < Tv, doL2 = p >= 1;
            float a1[2][4], a2[2][4];
#pragma unroll
            for (int g = 0; g < 2; g++) {
                float b0 = sb[g * 8 + 2 * c4], b1 = sb[g * 8 + 2 * c4 + 1];
                a1[g][0] = b0; a1[g][1] = b1; a1[g][2] = b0; a1[g][3] = b1;
                float d0 = sb[16 + g * 8 + 2 * c4], d1 = sb[16 + g * 8 + 2 * c4 + 1];
                a2[g][0] = d0; a2[g][1] = d1; a2[g][2] = d0; a2[g][3] = d1;
            }
            const int cstart = doL1 ? 0 : 1, cend = doL2 ? 9 : 5;
            for (int c = cstart; c < cend; c++) {
                const unsigned sl = gidx & 3;
                mbar_wait(fullb0 + sl * 8, (phbits >> sl) & 1u);
                phbits ^= (1u << sl);
                const int nsub = (c == 0) ? 1 : 2;
                for (int s2 = 0; s2 < nsub; s2++) {
                    const __half* ar0 = chunks + sl * BIGH_W + s2 * HC_W + r0 * GW + 2 * c4;
                    const __half* ar1 = chunks + sl * BIGH_W + s2 * HC_W + r1 * GW + 2 * c4;
                    // k offsets in each layer's weights for this sub-chunk
                    const int kb1 = (c == 0) ? 0 : 64 + (c - 1) * 128 + s2 * 64;   // L1
                    const int kb2 = (c <= 4) ? (c - 1) * 128 + s2 * 64
                                             : 512 + (c - 5) * 128 + s2 * 64;      // L2
                    const bool useL1 = doL1 && (c <= 4);
                    const bool useL2 = doL2 && (c >= 1);
#pragma unroll
                    for (int kc = 0; kc < 64; kc += 16) {
                        unsigned a0 = *(const unsigned*)(ar0 + kc);
                        unsigned aa1 = *(const unsigned*)(ar1 + kc);
                        unsigned a2r = *(const unsigned*)(ar0 + kc + 8);
                        unsigned a3 = *(const unsigned*)(ar1 + kc + 8);
                        if (useL1) {
#pragma unroll
                            for (int g = 0; g < 2; g++) {
                                const __half* bp = swl1 + (g * 8 + q) * K1PH + kb1 + kc + 2 * c4;
                                unsigned b0 = *(const unsigned*)bp;
                                unsigned b1 = *(const unsigned*)(bp + 8);
                                asm volatile(
                                    "mma.sync.aligned.m16n8k16.row.col.f32.f16.f16.f32 "
                                    "{%0,%1,%2,%3},{%4,%5,%6,%7},{%8,%9},{%0,%1,%2,%3};"
                                    : "+f"(a1[g][0]), "+f"(a1[g][1]),
                                      "+f"(a1[g][2]), "+f"(a1[g][3])
                                    : "r"(a0), "r"(aa1), "r"(a2r), "r"(a3), "r"(b0), "r"(b1));
                            }
                        }
                        if (useL2) {
#pragma unroll
                            for (int g = 0; g < 2; g++) {
                                const __half* bp = swl2 + (g * 8 + q) * K2PH + kb2 + kc + 2 * c4;
                                unsigned b0 = *(const unsigned*)bp;
                                unsigned b1 = *(const unsigned*)(bp + 8);
                                asm volatile(
                                    "mma.sync.aligned.m16n8k16.row.col.f32.f16.f16.f32 "
                                    "{%0,%1,%2,%3},{%4,%5,%6,%7},{%8,%9},{%0,%1,%2,%3};"
                                    : "+f"(a2[g][0]), "+f"(a2[g][1]),
                                      "+f"(a2[g][2]), "+f"(a2[g][3])
                                    : "r"(a0), "r"(aa1), "r"(a2r), "r"(a3), "r"(b0), "r"(b1));
                            }
                        }
                    }
                }
                if (lane == 0) mbar_arrive(consb0 + sl * 8);
                gidx++;
            }

            // ---- epilogues: shfl-gather gates, c update, fp16 h store ----
            const bool odd = (c4 & 1) != 0;
#pragma unroll
            for (int layer = 0; layer < 2; layer++) {
                if (layer == 0 ? !doL1 : !doL2) continue;
                float (*a)[4] = layer ? a2 : a1;
                __half* hout = layer
                    ? g_h2all + ((size_t)p * 2 + s) * 8 * HC_W + ch * HC_W + colbase
                    : &g_h1[p & (H1D - 1)][s][ch][0][colbase];
#pragma unroll
                for (int pr = 0; pr < 2; pr++) {
                    float sh0 = __shfl_xor_sync(0xffffffffu, a[pr][0], 1);
                    float sh1 = __shfl_xor_sync(0xffffffffu, a[pr][1], 1);
                    float sh2 = __shfl_xor_sync(0xffffffffu, a[pr][2], 1);
                    float sh3 = __shfl_xor_sync(0xffffffffu, a[pr][3], 1);
                    const int ul = pr * 2 + (c4 >> 1);
#pragma unroll
                    for (int rr = 0; rr < 2; rr++) {
                        float va = rr ? a[pr][2] : a[pr][0];
                        float vb = rr ? a[pr][3] : a[pr][1];
                        float wa = rr ? sh2 : sh0;
                        float wb = rr ? sh3 : sh1;
                        float gi = odd ? wa : va;
                        float gf = odd ? wb : vb;
                        float gg = odd ? va : wa;
                        float go = odd ? vb : wb;
                        float iv = sigm(gi), fv = sigm(gf);
                        float gv = tanh_(gg), ov = sigm(go);
                        int lr = rr ? r1 : r0;
                        float* cp = &sc[((layer * 128 + s * 64 + lr) << 2) + ul];
                        float cn = fv * *cp + iv * gv;
                        *cp = cn;
                        hout[(size_t)lr * GW + ul] = __float2half_rn(ov * tanh_(cn));
                    }
                }
            }
            // per-stream compute barrier, then publish stream flag
            if (s == 0) asm volatile("bar.sync 1, 128;" ::: "memory");
            else        asm volatile("bar.sync 2, 128;" ::: "memory");
            if (wl == 0 && lane == 0) {
                __threadfence();
                st_rel(myflag, E0 + (unsigned)p + 2u);
            }
        }
    }
}

// Post-pass: out[b][t][o] = h2(t)[b] . w_out[o] + b_out[o]  (h2(t) in slot t+1)
__global__ void __launch_bounds__(256)
out_gemm(const float* __restrict__ w_out, const float* __restrict__ b_out,
         float* __restrict__ out) {
    __shared__ __align__(16) float As[32 * OW];
    __shared__ __align__(16) float Bs[32 * OW];
    const int b = blockIdx.y;
    const int t0 = blockIdx.x * 64;
    const int tx = threadIdx.x;
    const int to = (tx & 15) * 4;
    const int tt = (tx >> 4) * 4;
    const int bs = b >> 6, blr = b & 63;
    float acc[4][4] = {};
    for (int k0 = 0; k0 < Hv; k0 += 32) {
        for (int i = tx; i < 512; i += 256) {
            int row = i >> 3, kq = (i & 7) * 4;
            const __half* src = g_h2all + ((size_t)(t0 + row + 1) * 2 + bs) * 8 * HC_W
                              + (k0 >> 6) * HC_W + (size_t)blr * GW + (k0 & 63) + kq;
            float2 f0 = __half22float2(*(const __half2*)(src));
            float2 f1 = __half22float2(*(const __half2*)(src + 2));
            As[(kq + 0) * OW + row] = f0.x;
            As[(kq + 1) * OW + row] = f0.y;
            As[(kq + 2) * OW + row] = f1.x;
            As[(kq + 3) * OW + row] = f1.y;
        }
        for (int i = tx; i < 512; i += 256) {
            int o = i >> 3, kq = (i & 7) * 4;
            float4 v = *(const float4*)(w_out + (size_t)o * Hv + k0 + kq);
            Bs[(kq + 0) * OW + o] = v.x;
            Bs[(kq + 1) * OW + o] = v.y;
            Bs[(kq + 2) * OW + o] = v.z;
            Bs[(kq + 3) * OW + o] = v.w;
        }
        __syncthreads();
#pragma unroll
        for (int k = 0; k < 32; k++) {
            float4 a = *(const float4*)(As + k * OW + tt);
            float4 w = *(const float4*)(Bs + k * OW + to);
            acc[0][0] = fmaf(a.x, w.x, acc[0][0]); acc[0][1] = fmaf(a.x, w.y, acc[0][1]);
            acc[0][2] = fmaf(a.x, w.z, acc[0][2]); acc[0][3] = fmaf(a.x, w.w, acc[0][3]);
            acc[1][0] = fmaf(a.y, w.x, acc[1][0]); acc[1][1] = fmaf(a.y, w.y, acc[1][1]);
            acc[1][2] = fmaf(a.y, w.z, acc[1][2]); acc[1][3] = fmaf(a.y, w.w, acc[1][3]);
            acc[2][0] = fmaf(a.z, w.x, acc[2][0]); acc[2][1] = fmaf(a.z, w.y, acc[2][1]);
            acc[2][2] = fmaf(a.z, w.z, acc[2][2]); acc[2][3] = fmaf(a.z, w.w, acc[2][3]);
            acc[3][0] = fmaf(a.w, w.x, acc[3][0]); acc[3][1] = fmaf(a.w, w.y, acc[3][1]);
            acc[3][2] = fmaf(a.w, w.z, acc[3][2]); acc[3][3] = fmaf(a.w, w.w, acc[3][3]);
        }
        __syncthreads();
    }
    float bo0 = b_out[to + 0], bo1 = b_out[to + 1], bo2 = b_out[to + 2], bo3 = b_out[to + 3];
#pragma unroll
    for (int i = 0; i < 4; i++) {
        float4 r;
        r.x = acc[i][0] + bo0; r.y = acc[i][1] + bo1;
        r.z = acc[i][2] + bo2; r.w = acc[i][3] + bo3;
        *(float4*)(out + ((size_t)b * Tv + t0 + tt + i) * DOUT + to) = r;
    }
}

extern "C" void kernel_launch(void* const* d_in, const int* in_sizes, int n_in,
                              void* d_out, int out_size) {
    (void)in_sizes; (void)n_in; (void)out_size;
    const float* x     = (const float*)d_in[0];
    const float* w_ih1 = (const float*)d_in[1];
    const float* w_hh1 = (const float*)d_in[2];
    const float* b_ih1 = (const float*)d_in[3];
    const float* b_hh1 = (const float*)d_in[4];
    const float* w_ih2 = (const float*)d_in[5];
    const float* w_hh2 = (const float*)d_in[6];
    const float* b_ih2 = (const float*)d_in[7];
    const float* b_hh2 = (const float*)d_in[8];
    const float* w_out = (const float*)d_in[9];
    const float* b_out = (const float*)d_in[10];

    xpose<<<Tv, 256>>>(x);
    cudaFuncSetAttribute(lstm_kernel, cudaFuncAttributeMaxDynamicSharedMemorySize, SMEM_BYTES);
    lstm_kernel<<<NCTA, NTHR, SMEM_BYTES>>>(w_ih1, w_hh1, b_ih1, b_hh1,
                                            w_ih2, w_hh2, b_ih2, b_hh2);
    out_gemm<<<dim3(Tv / 64, Bv), 256>>>(w_out, b_out, (float*)d_out);
}